// round 6
// baseline (speedup 1.0000x reference)
#include <cuda_runtime.h>
#include <cuda_bf16.h>
#include <cstdint>

// ---------------------------------------------------------------------------
// TotalAttention (Swin window attention), 3xBF16 pipeline, A-resident GEMMs:
//   0) pack_w: wq(*scale)|wkv -> transposed split planes [768][256]; wp ->
//      [256][256]; biases; bias table g_bias[h][n][m]
//   1) gemm_ar (A=x fp32, split in-kernel): qkv = x @ wqkv + bqkv -> fp32
//   2) attn (512 thr, 2 warps/head, 3xTF32) -> ao bf16 hi/res planes
//   3) gemm_ar (A=ao planes): out = ao @ wp + bp -> d_out fp32
// ---------------------------------------------------------------------------

#define B_WIN   4096
#define N_TOK   64
#define DIM_C   256
#define HEADS   8
#define HDIM    32
#define M_ROWS  (B_WIN * N_TOK)        // 262144
#define QKV_LD  768
#define SCALE_F 0.17677669529663687f   // 32^-0.5

__device__ float g_qkv[(size_t)M_ROWS * QKV_LD];            // 805 MB fp32
__device__ unsigned short g_aohi [(size_t)M_ROWS * DIM_C];
__device__ unsigned short g_aores[(size_t)M_ROWS * DIM_C];
__device__ unsigned short g_wthi [QKV_LD * DIM_C];          // wqkv^T [768][256]
__device__ unsigned short g_wtres[QKV_LD * DIM_C];
__device__ unsigned short g_wpthi [DIM_C * DIM_C];          // wp^T [256][256]
__device__ unsigned short g_wptres[DIM_C * DIM_C];
__device__ float g_bqkv[QKV_LD];
__device__ float g_bias[HEADS * N_TOK * N_TOK];             // [h][n][m]

// ---------------------------------------------------------------------------
__device__ __forceinline__ void cp_async16(void* smem_dst, const void* gsrc) {
    unsigned saddr = (unsigned)__cvta_generic_to_shared(smem_dst);
    asm volatile("cp.async.cg.shared.global [%0], [%1], 16;\n"
                 :: "r"(saddr), "l"(gsrc));
}

__device__ __forceinline__ void mma_bf16(float* c, const unsigned* a, const unsigned* b) {
    asm volatile(
        "mma.sync.aligned.m16n8k16.row.col.f32.bf16.bf16.f32 "
        "{%0,%1,%2,%3}, {%4,%5,%6,%7}, {%8,%9}, {%0,%1,%2,%3};\n"
        : "+f"(c[0]), "+f"(c[1]), "+f"(c[2]), "+f"(c[3])
        : "r"(a[0]), "r"(a[1]), "r"(a[2]), "r"(a[3]),
          "r"(b[0]), "r"(b[1]));
}

__device__ __forceinline__ void mma_tf32(float* c, const unsigned* a, const unsigned* b) {
    asm volatile(
        "mma.sync.aligned.m16n8k8.row.col.f32.tf32.tf32.f32 "
        "{%0,%1,%2,%3}, {%4,%5,%6,%7}, {%8,%9}, {%0,%1,%2,%3};\n"
        : "+f"(c[0]), "+f"(c[1]), "+f"(c[2]), "+f"(c[3])
        : "r"(a[0]), "r"(a[1]), "r"(a[2]), "r"(a[3]),
          "r"(b[0]), "r"(b[1]));
}

__device__ __forceinline__ void tf32_split(float f, unsigned& hi, unsigned& res) {
    hi  = __float_as_uint(f) & 0xFFFFE000u;
    res = __float_as_uint(f - __uint_as_float(hi));
}

__device__ __forceinline__ void bf16_split(float f, unsigned short& hi, unsigned short& res) {
    __nv_bfloat16 h = __float2bfloat16_rn(f);
    float r = f - __bfloat162float(h);
    hi  = __bfloat16_as_ushort(h);
    res = __bfloat16_as_ushort(__float2bfloat16_rn(r));
}

__device__ __forceinline__ void bf16_split_pack(float a, float b, unsigned& hi, unsigned& res) {
    unsigned short ha, ra, hb, rb;
    bf16_split(a, ha, ra);
    bf16_split(b, hb, rb);
    hi  = (unsigned)ha | ((unsigned)hb << 16);
    res = (unsigned)ra | ((unsigned)rb << 16);
}

// ---------------------------------------------------------------------------
// pack_w: transposed split weight planes (q pre-scaled) + biases + bias table
// ---------------------------------------------------------------------------
__global__ void pack_w(const float* __restrict__ wq, const float* __restrict__ bq,
                       const float* __restrict__ wkv, const float* __restrict__ bkv,
                       const float* __restrict__ wp,
                       const float* __restrict__ rpb, const int* __restrict__ relidx)
{
    int i = blockIdx.x * blockDim.x + threadIdx.x;
    if (i < QKV_LD * DIM_C) {                 // wqkv^T: [n=768][k=256]
        int n = i / DIM_C, k = i % DIM_C;
        float v = (n < DIM_C) ? wq[k * DIM_C + n] * SCALE_F
                              : wkv[k * 512 + (n - DIM_C)];
        bf16_split(v, g_wthi[i], g_wtres[i]);
    }
    if (i < DIM_C * DIM_C) {                  // wp^T: [n=256][k=256]
        int n = i / DIM_C, k = i % DIM_C;
        bf16_split(wp[k * DIM_C + n], g_wpthi[i], g_wptres[i]);
    }
    if (i < QKV_LD) g_bqkv[i] = (i < DIM_C) ? bq[i] * SCALE_F : bkv[i - DIM_C];
    if (i < HEADS * N_TOK * N_TOK) {
        int h = i >> 12, nm = i & 4095;
        g_bias[i] = rpb[relidx[nm] * HEADS + h];
    }
}

// ---------------------------------------------------------------------------
// A-resident 3xBF16 GEMM: C[m, :] = A[m,:256] @ W[:, :]^T + bias
// Block = 128 rows x (ntiles*128) cols; A staged ONCE in smem as bf16 hi/res
// (from fp32 with in-kernel split, or from pre-split planes via cp.async);
// W ([n][k=256] hi/res planes) streamed in 128n x 32k slices, double-buffered.
// A smem stride 264 shorts (132 words, mod32=4 -> conflict-free frags);
// B smem stride 40 shorts (20 words -> conflict-free frags).
// ---------------------------------------------------------------------------
#define A_STRIDE 264
#define A_PLANE  (128 * A_STRIDE)         // 33792 shorts
#define B_STRIDE 40
#define B_PLANE  (128 * B_STRIDE)         // 5120 shorts
#define B_BUF    (2 * B_PLANE)            // hi+res
#define GEMM_SMEM ((2 * A_PLANE + 2 * B_BUF) * 2)   // 176128 bytes

__global__ __launch_bounds__(256)
void gemm_ar(const float* __restrict__ Afp32,
             const unsigned short* __restrict__ Aghi,
             const unsigned short* __restrict__ Agres,
             const unsigned short* __restrict__ Whi,
             const unsigned short* __restrict__ Wres,
             const float* __restrict__ bias, float* __restrict__ C,
             int ntiles)
{
    extern __shared__ __align__(16) unsigned short smu[];
    unsigned short* Ahi  = smu;
    unsigned short* Ares = smu + A_PLANE;
    unsigned short* Bbuf = smu + 2 * A_PLANE;   // [2][B_BUF]

    const int tid  = threadIdx.x;
    const int warp = tid >> 5, lane = tid & 31;
    const int wm = warp >> 2, wn = warp & 3;    // 2 x 4 warp grid
    const int g  = lane >> 2, t  = lane & 3;
    const size_t m0 = (size_t)blockIdx.x * 128;
    const int ldc = ntiles * 128;
    const int nslices = ntiles * 8;

    // ---- issue B slice s into buffer buf ----
    auto issue_B = [&](int s, int buf) {
        const int ntile = s >> 3, kt = s & 7;
        unsigned short* bh = Bbuf + buf * B_BUF;
        unsigned short* br = bh + B_PLANE;
        const size_t wbase = (size_t)(ntile * 128) * 256 + kt * 32;
#pragma unroll
        for (int j = 0; j < 2; j++) {
            const int c = tid * 2 + j;              // 0..511
            const int row = c >> 2, off = (c & 3) * 8;
            cp_async16(&bh[row * B_STRIDE + off], Whi  + wbase + row * 256 + off);
            cp_async16(&br[row * B_STRIDE + off], Wres + wbase + row * 256 + off);
        }
        asm volatile("cp.async.commit_group;\n");
    };

    issue_B(0, 0);

    // ---- A staging ----
    if (Afp32) {
        // fp32 source: load, split, store (fused split_x)
        for (int idx = tid; idx < 8192; idx += 256) {
            const int row = idx >> 6;
            const int c4  = (idx & 63) * 4;
            float4 v = *(const float4*)(Afp32 + (m0 + row) * 256 + c4);
            unsigned h0, r0w, h1, r1w;
            bf16_split_pack(v.x, v.y, h0, r0w);
            bf16_split_pack(v.z, v.w, h1, r1w);
            unsigned* ph = (unsigned*)&Ahi [row * A_STRIDE + c4];
            unsigned* pr = (unsigned*)&Ares[row * A_STRIDE + c4];
            ph[0] = h0; ph[1] = h1;
            pr[0] = r0w; pr[1] = r1w;
        }
    } else {
        // pre-split planes: cp.async
        for (int c = tid; c < 4096; c += 256) {
            const int row = c >> 5, off = (c & 31) * 8;
            cp_async16(&Ahi [row * A_STRIDE + off], Aghi  + (m0 + row) * 256 + off);
            cp_async16(&Ares[row * A_STRIDE + off], Agres + (m0 + row) * 256 + off);
        }
        asm volatile("cp.async.commit_group;\n");
    }

    float acc[4][4][4];
#pragma unroll
    for (int mt = 0; mt < 4; mt++)
#pragma unroll
        for (int nt = 0; nt < 4; nt++)
#pragma unroll
            for (int r = 0; r < 4; r++) acc[mt][nt][r] = 0.0f;

    for (int s = 0; s < nslices; ++s) {
        asm volatile("cp.async.wait_group 0;\n");
        __syncthreads();

        if (s + 1 < nslices) issue_B(s + 1, (s + 1) & 1);

        const unsigned short* Bh = Bbuf + (s & 1) * B_BUF;
        const unsigned short* Br = Bh + B_PLANE;
        const int kbase = (s & 7) * 32;

#pragma unroll
        for (int ks = 0; ks < 2; ++ks) {
            const int ck = kbase + ks * 16;
            const int bk = ks * 16;
            unsigned bhf[4][2], brf[4][2];
#pragma unroll
            for (int nt = 0; nt < 4; nt++) {
                const int np = wn * 32 + nt * 8 + g;
                const unsigned short* ph = Bh + np * B_STRIDE + bk + 2 * t;
                const unsigned short* pr = Br + np * B_STRIDE + bk + 2 * t;
                bhf[nt][0] = *(const unsigned*)ph;
                bhf[nt][1] = *(const unsigned*)(ph + 8);
                brf[nt][0] = *(const unsigned*)pr;
                brf[nt][1] = *(const unsigned*)(pr + 8);
            }
#pragma unroll
            for (int mt = 0; mt < 4; mt++) {
                const int r0 = wm * 64 + mt * 16 + g;
                const unsigned short* ph = Ahi  + r0 * A_STRIDE + ck + 2 * t;
                const unsigned short* pr = Ares + r0 * A_STRIDE + ck + 2 * t;
                unsigned ah[4], ar[4];
                ah[0] = *(const unsigned*)ph;
                ah[1] = *(const unsigned*)(ph + 8 * A_STRIDE);
                ah[2] = *(const unsigned*)(ph + 8);
                ah[3] = *(const unsigned*)(ph + 8 * A_STRIDE + 8);
                ar[0] = *(const unsigned*)pr;
                ar[1] = *(const unsigned*)(pr + 8 * A_STRIDE);
                ar[2] = *(const unsigned*)(pr + 8);
                ar[3] = *(const unsigned*)(pr + 8 * A_STRIDE + 8);
#pragma unroll
                for (int nt = 0; nt < 4; nt++) {
                    mma_bf16(acc[mt][nt], ar, bhf[nt]);
                    mma_bf16(acc[mt][nt], ah, brf[nt]);
                    mma_bf16(acc[mt][nt], ah, bhf[nt]);
                }
            }
        }

        // end of n-tile: bias + store + reset
        if ((s & 7) == 7) {
            const int ncol0 = (s >> 3) * 128;
#pragma unroll
            for (int mt = 0; mt < 4; mt++) {
                const size_t r0 = m0 + wm * 64 + mt * 16 + g;
#pragma unroll
                for (int nt = 0; nt < 4; nt++) {
                    const int col = ncol0 + wn * 32 + nt * 8 + 2 * t;
                    const float b0 = bias[col], b1 = bias[col + 1];
                    float* cp0 = C + r0 * ldc + col;
                    float* cp1 = C + (r0 + 8) * ldc + col;
                    *(float2*)cp0 = make_float2(acc[mt][nt][0] + b0, acc[mt][nt][1] + b1);
                    *(float2*)cp1 = make_float2(acc[mt][nt][2] + b0, acc[mt][nt][3] + b1);
#pragma unroll
                    for (int r = 0; r < 4; r++) acc[mt][nt][r] = 0.0f;
                }
            }
        }
    }
}

// ---------------------------------------------------------------------------
// Attention: block = window (512 threads), 2 warps per head (warp = 32 rows).
// Per-head smem: Q[64x32]@36 | K[64x32]@36 | V[64x32]@40 fp32; P@68 aliases Q+K.
// Pair sync via named barrier (1+h). 3xTF32 mma; softmax in registers.
// ---------------------------------------------------------------------------
#define QS_STRIDE 36
#define KS_STRIDE 36
#define VS_STRIDE 40
#define PS_STRIDE 68
#define HEAD_FLOATS (64 * QS_STRIDE + 64 * KS_STRIDE + 64 * VS_STRIDE)  // 7168
#define ATTN_SMEM (8 * HEAD_FLOATS * 4)   // 229376 bytes

__global__ __launch_bounds__(512, 1)
void attn_tc(const float* __restrict__ qkv,
             const float* __restrict__ bias)
{
    extern __shared__ float sm[];
    const int b    = blockIdx.x;
    const int warp = threadIdx.x >> 5;
    const int lane = threadIdx.x & 31;
    const int h    = warp >> 1;          // head
    const int half = warp & 1;           // row half: 0 -> rows 0..31, 1 -> 32..63
    const int g = lane >> 2, t = lane & 3;

    float* QS = sm + h * HEAD_FLOATS;
    float* KS = QS + 64 * QS_STRIDE;
    float* VS = KS + 64 * KS_STRIDE;
    float* PS = QS;                      // aliases Q+K (4352 <= 4608 floats)

    // ---- load Q/K/V head slices (q pre-scaled in gemm); 64 lanes per head ----
    const size_t base = (size_t)b * N_TOK * QKV_LD + h * HDIM;
    for (int i = half * 32 + lane; i < 512; i += 64) {
        const int row = i >> 3;
        const int c4  = (i & 7) << 2;
        const float* rp = qkv + base + (size_t)row * QKV_LD + c4;
        float4 q = *(const float4*)(rp);
        float4 k = *(const float4*)(rp + 256);
        float4 v = *(const float4*)(rp + 512);
        *(float4*)&QS[row * QS_STRIDE + c4] = q;
        *(float4*)&KS[row * KS_STRIDE + c4] = k;
        *(float4*)&VS[row * VS_STRIDE + c4] = v;
    }
    __syncthreads();

    // ---- S = Q @ K^T : rows half*32..+31 (mt 0..1), cols 64 (nt 0..7) ----
    float s_[2][8][4];
#pragma unroll
    for (int mt = 0; mt < 2; mt++)
#pragma unroll
        for (int nt = 0; nt < 8; nt++)
#pragma unroll
            for (int r = 0; r < 4; r++) s_[mt][nt][r] = 0.0f;

#pragma unroll
    for (int ks = 0; ks < 4; ++ks) {
        const int ck = ks * 8;
        unsigned ah[2][4], ar[2][4];
#pragma unroll
        for (int mt = 0; mt < 2; mt++) {
            const float* p = QS + (half * 32 + mt * 16 + g) * QS_STRIDE + ck + t;
            tf32_split(p[0],                 ah[mt][0], ar[mt][0]);
            tf32_split(p[8 * QS_STRIDE],     ah[mt][1], ar[mt][1]);
            tf32_split(p[4],                 ah[mt][2], ar[mt][2]);
            tf32_split(p[8 * QS_STRIDE + 4], ah[mt][3], ar[mt][3]);
        }
#pragma unroll
        for (int nt = 0; nt < 8; nt++) {
            const float* p = KS + (nt * 8 + g) * KS_STRIDE + ck + t;
            unsigned bh[2], br[2];
            tf32_split(p[0], bh[0], br[0]);
            tf32_split(p[4], bh[1], br[1]);
#pragma unroll
            for (int mt = 0; mt < 2; mt++) {
                mma_tf32(s_[mt][nt], ar[mt], bh);
                mma_tf32(s_[mt][nt], ah[mt], br);
                mma_tf32(s_[mt][nt], ah[mt], bh);
            }
        }
    }

    // ---- bias ----
    const float* bh_tab = bias + h * (N_TOK * N_TOK);
#pragma unroll
    for (int mt = 0; mt < 2; mt++) {
        const int r0 = half * 32 + mt * 16 + g;
#pragma unroll
        for (int nt = 0; nt < 8; nt++) {
            const int c = nt * 8 + 2 * t;
            float2 b0 = *(const float2*)&bh_tab[r0 * 64 + c];
            float2 b1 = *(const float2*)&bh_tab[(r0 + 8) * 64 + c];
            s_[mt][nt][0] += b0.x;  s_[mt][nt][1] += b0.y;
            s_[mt][nt][2] += b1.x;  s_[mt][nt][3] += b1.y;
        }
    }

    // ---- softmax per row ----
#pragma unroll
    for (int mt = 0; mt < 2; mt++) {
        float m0 = -1e30f, m1 = -1e30f;
#pragma unroll
        for (int nt = 0; nt < 8; nt++) {
            m0 = fmaxf(m0, fmaxf(s_[mt][nt][0], s_[mt][nt][1]));
            m1 = fmaxf(m1, fmaxf(s_[mt][nt][2], s_[mt][nt][3]));
        }
        m0 = fmaxf(m0, __shfl_xor_sync(0xffffffffu, m0, 1));
        m0 = fmaxf(m0, __shfl_xor_sync(0xffffffffu, m0, 2));
        m1 = fmaxf(m1, __shfl_xor_sync(0xffffffffu, m1, 1));
        m1 = fmaxf(m1, __shfl_xor_sync(0xffffffffu, m1, 2));
        float s0 = 0.0f, s1 = 0.0f;
#pragma unroll
        for (int nt = 0; nt < 8; nt++) {
            s_[mt][nt][0] = __expf(s_[mt][nt][0] - m0);
            s_[mt][nt][1] = __expf(s_[mt][nt][1] - m0);
            s_[mt][nt][2] = __expf(s_[mt][nt][2] - m1);
            s_[mt][nt][3] = __expf(s_[mt][nt][3] - m1);
            s0 += s_[mt][nt][0] + s_[mt][nt][1];
            s1 += s_[mt][nt][2] + s_[mt][nt][3];
        }
        s0 += __shfl_xor_sync(0xffffffffu, s0, 1);
        s0 += __shfl_xor_sync(0xffffffffu, s0, 2);
        s1 += __shfl_xor_sync(0xffffffffu, s1, 1);
        s1 += __shfl_xor_sync(0xffffffffu, s1, 2);
        const float i0 = __frcp_rn(s0), i1 = __frcp_rn(s1);
#pragma unroll
        for (int nt = 0; nt < 8; nt++) {
            s_[mt][nt][0] *= i0;  s_[mt][nt][1] *= i0;
            s_[mt][nt][2] *= i1;  s_[mt][nt][3] *= i1;
        }
    }

    // pair barrier: both warps done reading Q/K before P overwrites the region
    asm volatile("bar.sync %0, %1;" :: "r"(1 + h), "r"(64) : "memory");

    // ---- write P (own rows) ----
#pragma unroll
    for (int mt = 0; mt < 2; mt++) {
        const int r0 = half * 32 + mt * 16 + g;
#pragma unroll
        for (int nt = 0; nt < 8; nt++) {
            const int c = nt * 8 + 2 * t;
            *(float2*)&PS[r0 * PS_STRIDE + c]       = make_float2(s_[mt][nt][0], s_[mt][nt][1]);
            *(float2*)&PS[(r0 + 8) * PS_STRIDE + c] = make_float2(s_[mt][nt][2], s_[mt][nt][3]);
        }
    }
    // pair barrier: all P rows visible before PV reads
    asm volatile("bar.sync %0, %1;" :: "r"(1 + h), "r"(64) : "memory");

    // ---- O = P @ V : rows half*32..+31 (mt 0..1), cols 32 (nt 0..3) ----
    float o[2][4][4];
#pragma unroll
    for (int mt = 0; mt < 2; mt++)
#pragma unroll
        for (int nt = 0; nt < 4; nt++)
#pragma unroll
            for (int r = 0; r < 4; r++) o[mt][nt][r] = 0.0f;

#pragma unroll
    for (int ks = 0; ks < 8; ++ks) {
        const int ck = ks * 8;
        unsigned ah[2][4], ar[2][4];
#pragma unroll
        for (int mt = 0; mt < 2; mt++) {
            const float* p = PS + (half * 32 + mt * 16 + g) * PS_STRIDE + ck + t;
            tf32_split(p[0],                 ah[mt][0], ar[mt][0]);
            tf32_split(p[8 * PS_STRIDE],     ah[mt][1], ar[mt][1]);
            tf32_split(p[4],                 ah[mt][2], ar[mt][2]);
            tf32_split(p[8 * PS_STRIDE + 4], ah[mt][3], ar[mt][3]);
        }
#pragma unroll
        for (int nt = 0; nt < 4; nt++) {
            const float* p = VS + (ck + t) * VS_STRIDE + nt * 8 + g;
            unsigned bh[2], br[2];
            tf32_split(p[0],             bh[0], br[0]);
            tf32_split(p[4 * VS_STRIDE], bh[1], br[1]);
#pragma unroll
            for (int mt = 0; mt < 2; mt++) {
                mma_tf32(o[mt][nt], ar[mt], bh);
                mma_tf32(o[mt][nt], ah[mt], br);
                mma_tf32(o[mt][nt], ah[mt], bh);
            }
        }
    }

    // ---- store O as bf16 hi/res planes ----
#pragma unroll
    for (int mt = 0; mt < 2; mt++) {
        const int r0 = half * 32 + mt * 16 + g;
#pragma unroll
        for (int nt = 0; nt < 4; nt++) {
            const int col = h * HDIM + nt * 8 + 2 * t;
            const size_t e0 = ((size_t)b * N_TOK + r0)     * DIM_C + col;
            const size_t e1 = ((size_t)b * N_TOK + r0 + 8) * DIM_C + col;
            unsigned hi, res;
            bf16_split_pack(o[mt][nt][0], o[mt][nt][1], hi, res);
            ((unsigned*)g_aohi)[e0 >> 1]  = hi;
            ((unsigned*)g_aores)[e0 >> 1] = res;
            bf16_split_pack(o[mt][nt][2], o[mt][nt][3], hi, res);
            ((unsigned*)g_aohi)[e1 >> 1]  = hi;
            ((unsigned*)g_aores)[e1 >> 1] = res;
        }
    }
}

// ---------------------------------------------------------------------------
extern "C" void kernel_launch(void* const* d_in, const int* in_sizes, int n_in,
                              void* d_out, int out_size)
{
    const float* x      = (const float*)d_in[0];
    const float* wq     = (const float*)d_in[1];
    const float* bq     = (const float*)d_in[2];
    const float* wkv    = (const float*)d_in[3];
    const float* bkv    = (const float*)d_in[4];
    const float* wp     = (const float*)d_in[5];
    const float* bp     = (const float*)d_in[6];
    const float* rpb    = (const float*)d_in[7];
    const int*   relidx = (const int*)  d_in[8];
    float* out = (float*)d_out;

    float *qkv = nullptr, *bqkv = nullptr, *bias = nullptr;
    unsigned short *aohi, *aores, *wthi, *wtres, *wpthi, *wptres;
    cudaGetSymbolAddress((void**)&qkv,    g_qkv);
    cudaGetSymbolAddress((void**)&bqkv,   g_bqkv);
    cudaGetSymbolAddress((void**)&bias,   g_bias);
    cudaGetSymbolAddress((void**)&aohi,   g_aohi);
    cudaGetSymbolAddress((void**)&aores,  g_aores);
    cudaGetSymbolAddress((void**)&wthi,   g_wthi);
    cudaGetSymbolAddress((void**)&wtres,  g_wtres);
    cudaGetSymbolAddress((void**)&wpthi,  g_wpthi);
    cudaGetSymbolAddress((void**)&wptres, g_wptres);

    cudaFuncSetAttribute(gemm_ar, cudaFuncAttributeMaxDynamicSharedMemorySize, GEMM_SMEM);
    cudaFuncSetAttribute(attn_tc, cudaFuncAttributeMaxDynamicSharedMemorySize, ATTN_SMEM);

    // 0) pack weights (q pre-scaled) + bias table
    pack_w<<<(QKV_LD * DIM_C + 255) / 256, 256>>>(wq, bq, wkv, bkv, wp, rpb, relidx);

    // 1) qkv = x @ wqkv + bqkv  (A = fp32 x, split in-kernel; 6 n-tiles)
    gemm_ar<<<M_ROWS / 128, 256, GEMM_SMEM>>>(x, nullptr, nullptr,
                                              wthi, wtres, bqkv, qkv, 6);

    // 2) attention
    attn_tc<<<B_WIN, 512, ATTN_SMEM>>>(qkv, bias);

    // 3) out = ao @ wp + bp  (A = pre-split ao planes; 2 n-tiles)
    gemm_ar<<<M_ROWS / 128, 256, GEMM_SMEM>>>(nullptr, aohi, aores,
                                              wpthi, wptres, bp, out, 2);
}